// round 11
// baseline (speedup 1.0000x reference)
#include <cuda_runtime.h>
#include <cstdint>

// ---------------------------------------------------------------------------
// DLRM forward, fp32 with f32x2-packed (FFMA2) GEMM inner loops.
// R10 (resubmitted): R8's validated GEMM body (register prefetch + 2 syncs
// per tile); big layers as 64x64 tiles / 128 threads -> 1024/512-CTA grids
// for 4-6 CTAs/SM. (R9's ping-pong rewrite blew regs to 236 and regressed.)
// Pipeline:
//   init: detect int64 vs int32 indices + build pair LUT (device side)
//   bot MLP: 13->512->256->64    -> writes R[:,0:64]
//   interaction (FUSED gather+mean+351 pairwise dots) -> R[:,64:415]
//   top MLP: 415->512->256, 256->1 (warp GEMV)        -> d_out
// ---------------------------------------------------------------------------

#define BATCH 8192
#define NTAB  26
#define DDIM  64
#define LBAG  4
#define NROWS 100001
#define NFEAT 27           // 1 + NTAB
#define NPAIR 351          // 27*26/2
#define RCOLS 415          // 64 + 351

// Scratch (static device allocations only — no cudaMalloc allowed)
__device__ float g_h0[BATCH * 512];
__device__ float g_h1[BATCH * 256];
__device__ float g_R [(size_t)BATCH * RCOLS];
__device__ float g_t0[BATCH * 512];
__device__ float g_t1[BATCH * 256];
__device__ int   g_is64;
__device__ unsigned char g_pi[NPAIR];
__device__ unsigned char g_pj[NPAIR];

// ---------------------------------------------------------------------------
// f32x2 packed helpers (FFMA2 — ptxas never emits this from C++)
// ---------------------------------------------------------------------------
union F4U { float4 f; unsigned long long u[2]; };

__device__ __forceinline__ unsigned long long pack2(float x, float y) {
    unsigned long long r;
    asm("mov.b64 %0, {%1, %2};" : "=l"(r) : "f"(x), "f"(y));
    return r;
}
__device__ __forceinline__ void unpack2(unsigned long long v, float& x, float& y) {
    asm("mov.b64 {%0, %1}, %2;" : "=f"(x), "=f"(y) : "l"(v));
}
__device__ __forceinline__ unsigned long long ffma2(unsigned long long a,
                                                    unsigned long long b,
                                                    unsigned long long c) {
    unsigned long long d;
    asm("fma.rn.f32x2 %0, %1, %2, %3;" : "=l"(d) : "l"(a), "l"(b), "l"(c));
    return d;
}

// ---------------------------------------------------------------------------
// Init: (a) index dtype detection — int64 buffer => first 64 values all in
// [0, 100000]; int32 read as int64 => (lo | hi<<32) out of range. (b) tril LUT.
// ---------------------------------------------------------------------------
__global__ void init_kernel(const long long* __restrict__ lsi) {
    if (threadIdx.x == 0) {
        int ok = 1;
        for (int i = 0; i < 64; i++) {
            long long v = lsi[i];
            if (v < 0 || v > 100000) { ok = 0; break; }
        }
        g_is64 = ok;
        int p = 0;
        for (int i = 1; i < NFEAT; i++)
            for (int j = 0; j < i; j++) {
                g_pi[p] = (unsigned char)i;
                g_pj[p] = (unsigned char)j;
                p++;
            }
    }
}

// ---------------------------------------------------------------------------
// Tiled SGEMM (R8-validated body):
//   C[m, n] = act( sum_k A[m*K+k] * W[n*K+k] + bias[n] ),  C stride = ldc.
// Register prefetch of tile t+1 during tile t compute; single smem buffer,
// two __syncthreads per tile. Acc packed 2-wide along M (FFMA2).
// launch_bounds(THREADS, 512/THREADS) -> uniform 128-reg cap (satisfiable).
// ---------------------------------------------------------------------------
template<int BM, int BN, int BK, int TM, int TN, bool RELU>
__global__ void __launch_bounds__((BM / TM) * (BN / TN), 512 / ((BM / TM) * (BN / TN)))
sgemm_bias_act(const float* __restrict__ A, const float* __restrict__ W,
               const float* __restrict__ bias, float* __restrict__ C,
               int M, int N, int K, int ldc)
{
    constexpr int THREADS = (BM / TM) * (BN / TN);
    constexpr int LA = BM * BK / THREADS;    // per-thread A elements per tile
    constexpr int LW = BN * BK / THREADS;    // per-thread W elements per tile
    __shared__ float As[BK][BM + 4];
    __shared__ float Ws[BK][BN + 4];

    const int tid  = threadIdx.x;
    const int tx   = tid % (BN / TN);
    const int ty   = tid / (BN / TN);
    const int row0 = ty * TM;
    const int col0 = tx * TN;
    const int mBase = blockIdx.y * BM;
    const int nBase = blockIdx.x * BN;

    unsigned long long acc[TM / 2][TN];
    #pragma unroll
    for (int i = 0; i < TM / 2; i++)
        #pragma unroll
        for (int j = 0; j < TN; j++) acc[i][j] = 0ull;   // bits of (0.f,0.f)

    float pa[LA], pw[LW];

    // Prefetch tile 0 into registers
    {
        #pragma unroll
        for (int q = 0; q < LA; q++) {
            int e = tid + q * THREADS;
            int k = e % BK, m = e / BK;
            pa[q] = (k < K) ? A[(size_t)(mBase + m) * K + k] : 0.f;
        }
        #pragma unroll
        for (int q = 0; q < LW; q++) {
            int e = tid + q * THREADS;
            int k = e % BK, n = e / BK;
            int gn = nBase + n;
            pw[q] = (k < K && gn < N) ? W[(size_t)gn * K + k] : 0.f;
        }
    }

    const int nTiles = (K + BK - 1) / BK;
    for (int t = 0; t < nTiles; t++) {
        // Commit prefetched tile to smem
        #pragma unroll
        for (int q = 0; q < LA; q++) {
            int e = tid + q * THREADS;
            As[e % BK][e / BK] = pa[q];
        }
        #pragma unroll
        for (int q = 0; q < LW; q++) {
            int e = tid + q * THREADS;
            Ws[e % BK][e / BK] = pw[q];
        }
        __syncthreads();

        // Prefetch next tile while computing this one
        if (t + 1 < nTiles) {
            int k0 = (t + 1) * BK;
            #pragma unroll
            for (int q = 0; q < LA; q++) {
                int e = tid + q * THREADS;
                int k = e % BK, m = e / BK;
                int gk = k0 + k;
                pa[q] = (gk < K) ? A[(size_t)(mBase + m) * K + gk] : 0.f;
            }
            #pragma unroll
            for (int q = 0; q < LW; q++) {
                int e = tid + q * THREADS;
                int k = e % BK, n = e / BK;
                int gk = k0 + k, gn = nBase + n;
                pw[q] = (gk < K && gn < N) ? W[(size_t)gn * K + gk] : 0.f;
            }
        }

        #pragma unroll
        for (int kk = 0; kk < BK; kk++) {
            F4U a[TM / 4], w[TN / 4];
            #pragma unroll
            for (int q = 0; q < TM / 4; q++)
                a[q].f = *(const float4*)&As[kk][row0 + 4 * q];
            #pragma unroll
            for (int q = 0; q < TN / 4; q++)
                w[q].f = *(const float4*)&Ws[kk][col0 + 4 * q];

            unsigned long long au[TM / 2], bw[TN];
            #pragma unroll
            for (int q = 0; q < TM / 4; q++) {
                au[2 * q]     = a[q].u[0];     // pairs (m, m+1) straight from LDS.128
                au[2 * q + 1] = a[q].u[1];
            }
            #pragma unroll
            for (int q = 0; q < TN / 4; q++) {
                bw[4 * q + 0] = pack2(w[q].f.x, w[q].f.x);
                bw[4 * q + 1] = pack2(w[q].f.y, w[q].f.y);
                bw[4 * q + 2] = pack2(w[q].f.z, w[q].f.z);
                bw[4 * q + 3] = pack2(w[q].f.w, w[q].f.w);
            }
            #pragma unroll
            for (int mp = 0; mp < TM / 2; mp++)
                #pragma unroll
                for (int j = 0; j < TN; j++)
                    acc[mp][j] = ffma2(au[mp], bw[j], acc[mp][j]);
        }
        __syncthreads();
    }

    // Epilogue: bias + relu, scalar stores (ldc may be odd, e.g. 415)
    float bv[TN];
    #pragma unroll
    for (int j = 0; j < TN; j++) {
        int gn = nBase + col0 + j;
        bv[j] = (gn < N) ? bias[gn] : 0.f;
    }
    #pragma unroll
    for (int mp = 0; mp < TM / 2; mp++) {
        #pragma unroll
        for (int j = 0; j < TN; j++) {
            int gn = nBase + col0 + j;
            if (gn < N) {
                float c0, c1;
                unpack2(acc[mp][j], c0, c1);
                c0 += bv[j]; c1 += bv[j];
                if (RELU) { c0 = fmaxf(c0, 0.f); c1 = fmaxf(c1, 0.f); }
                size_t o = (size_t)(mBase + row0 + 2 * mp) * ldc + gn;
                C[o]       = c0;
                C[o + ldc] = c1;
            }
        }
    }
}

// ---------------------------------------------------------------------------
// FUSED gather + interaction. One block per batch row b.
// ---------------------------------------------------------------------------
__global__ void __launch_bounds__(384)
interact_kernel(const void* __restrict__ lsi_raw,
                const float* __restrict__ emb,
                float* __restrict__ R)
{
    __shared__ float T[NFEAT][68];
    __shared__ int   rowIdx[NTAB][LBAG];
    const int b = blockIdx.x;

    if (threadIdx.x < NTAB * LBAG) {
        const int t = threadIdx.x >> 2;
        const int l = threadIdx.x & 3;
        const long long ib = (long long)t * (BATCH * LBAG) + (long long)b * LBAG + l;
        long long r = (g_is64 != 0) ? ((const long long*)lsi_raw)[ib]
                                    : (long long)((const int*)lsi_raw)[ib];
        rowIdx[t][l] = (int)r;
    }
    for (int d = threadIdx.x; d < DDIM; d += 384)
        T[0][d] = R[(size_t)b * RCOLS + d];
    __syncthreads();

    for (int e = threadIdx.x; e < NTAB * (DDIM / 2); e += 384) {
        const int t  = e >> 5;
        const int d2 = e & 31;
        const float2* tab = (const float2*)(emb + (size_t)t * NROWS * DDIM) + d2;
        float sx = 0.f, sy = 0.f;
        #pragma unroll
        for (int l = 0; l < LBAG; l++) {
            float2 v = __ldg(tab + (size_t)rowIdx[t][l] * (DDIM / 2));
            sx += v.x; sy += v.y;
        }
        *(float2*)&T[1 + t][2 * d2] = make_float2(sx * 0.25f, sy * 0.25f);
    }
    __syncthreads();

    const int p = threadIdx.x;
    if (p < NPAIR) {
        const int i = __ldg(&g_pi[p]);
        const int j = __ldg(&g_pj[p]);
        const float4* ti = (const float4*)T[i];
        const float4* tj = (const float4*)T[j];
        float s = 0.f;
        #pragma unroll
        for (int k = 0; k < DDIM / 4; k++) {
            float4 a = ti[k], c = tj[k];
            s += a.x * c.x + a.y * c.y + a.z * c.z + a.w * c.w;
        }
        R[(size_t)b * RCOLS + DDIM + p] = s;
    }
}

// ---------------------------------------------------------------------------
// Final layer: z[b] = dot(t1[b, :256], w2) + b2. One warp per row.
// ---------------------------------------------------------------------------
__global__ void final_kernel(const float* __restrict__ t1,
                             const float* __restrict__ w2,
                             const float* __restrict__ b2,
                             float* __restrict__ out)
{
    const int warp = threadIdx.x >> 5;
    const int lane = threadIdx.x & 31;
    const int b = blockIdx.x * 8 + warp;

    const float4* x = (const float4*)(t1 + (size_t)b * 256);
    const float4* w = (const float4*)w2;
    float s = 0.f;
    #pragma unroll
    for (int k = lane; k < 64; k += 32) {
        float4 a = x[k], c = w[k];
        s += a.x * c.x + a.y * c.y + a.z * c.z + a.w * c.w;
    }
    #pragma unroll
    for (int off = 16; off; off >>= 1)
        s += __shfl_xor_sync(0xFFFFFFFFu, s, off);
    if (lane == 0) out[b] = s + b2[0];
}

// ---------------------------------------------------------------------------
// Launch
// ---------------------------------------------------------------------------
extern "C" void kernel_launch(void* const* d_in, const int* in_sizes, int n_in,
                              void* d_out, int out_size)
{
    const float* dense = (const float*)d_in[0];
    const void*  lsi   = d_in[2];                 // int64 or int32 (detected)
    const float* emb   = (const float*)d_in[3];
    const float* bw0 = (const float*)d_in[4];
    const float* bb0 = (const float*)d_in[5];
    const float* bw1 = (const float*)d_in[6];
    const float* bb1 = (const float*)d_in[7];
    const float* bw2 = (const float*)d_in[8];
    const float* bb2 = (const float*)d_in[9];
    const float* tw0 = (const float*)d_in[10];
    const float* tb0 = (const float*)d_in[11];
    const float* tw1 = (const float*)d_in[12];
    const float* tb1 = (const float*)d_in[13];
    const float* tw2 = (const float*)d_in[14];
    const float* tb2 = (const float*)d_in[15];

    float *h0, *h1, *R, *t0, *t1;
    cudaGetSymbolAddress((void**)&h0, g_h0);
    cudaGetSymbolAddress((void**)&h1, g_h1);
    cudaGetSymbolAddress((void**)&R,  g_R);
    cudaGetSymbolAddress((void**)&t0, g_t0);
    cudaGetSymbolAddress((void**)&t1, g_t1);

    init_kernel<<<1, 1>>>((const long long*)lsi);

    // Bottom MLP: 13 -> 512 -> 256 -> 64 (last layer writes R[:, 0:64])
    sgemm_bias_act<64, 64, 16, 4, 8, true><<<dim3(8, 128), 128>>>(
        dense, bw0, bb0, h0, BATCH, 512, 13, 512);
    sgemm_bias_act<64, 64, 16, 4, 8, true><<<dim3(4, 128), 128>>>(
        h0, bw1, bb1, h1, BATCH, 256, 512, 256);
    sgemm_bias_act<32, 64, 16, 4, 4, true><<<dim3(1, 256), 128>>>(
        h1, bw2, bb2, R, BATCH, 64, 256, RCOLS);

    // Fused gather + pairwise interaction -> R[:, 64:415]
    interact_kernel<<<BATCH, 384>>>(lsi, emb, R);

    // Top MLP: 415 -> 512 -> 256 -> 1
    sgemm_bias_act<64, 64, 16, 4, 8, true><<<dim3(8, 128), 128>>>(
        R, tw0, tb0, t0, BATCH, 512, RCOLS, 512);
    sgemm_bias_act<64, 64, 16, 4, 8, true><<<dim3(4, 128), 128>>>(
        t0, tw1, tb1, t1, BATCH, 256, 512, 256);
    final_kernel<<<BATCH / 8, 256>>>(t1, tw2, tb2, (float*)d_out);
}

// round 14
// speedup vs baseline: 1.3047x; 1.3047x over previous
#include <cuda_runtime.h>
#include <cstdint>

// ---------------------------------------------------------------------------
// DLRM forward, fp32 with f32x2-packed (FFMA2) GEMM inner loops.
// R12 (3rd submission; prior two hit GPU acquisition timeouts): R8-exact
// configuration (validated 355us) with ONE change — BK=32 on the three
// large-K layers (bot2, top1, top2) to halve barrier count.
// Pipeline:
//   init: detect int64 vs int32 indices + build pair LUT (device side)
//   bot MLP: 13->512->256->64    -> writes R[:,0:64]
//   interaction (FUSED gather+mean+351 pairwise dots) -> R[:,64:415]
//   top MLP: 415->512->256, 256->1 (warp GEMV)        -> d_out
// ---------------------------------------------------------------------------

#define BATCH 8192
#define NTAB  26
#define DDIM  64
#define LBAG  4
#define NROWS 100001
#define NFEAT 27           // 1 + NTAB
#define NPAIR 351          // 27*26/2
#define RCOLS 415          // 64 + 351

// Scratch (static device allocations only — no cudaMalloc allowed)
__device__ float g_h0[BATCH * 512];
__device__ float g_h1[BATCH * 256];
__device__ float g_R [(size_t)BATCH * RCOLS];
__device__ float g_t0[BATCH * 512];
__device__ float g_t1[BATCH * 256];
__device__ int   g_is64;
__device__ unsigned char g_pi[NPAIR];
__device__ unsigned char g_pj[NPAIR];

// ---------------------------------------------------------------------------
// f32x2 packed helpers (FFMA2 — ptxas never emits this from C++)
// ---------------------------------------------------------------------------
union F4U { float4 f; unsigned long long u[2]; };

__device__ __forceinline__ unsigned long long pack2(float x, float y) {
    unsigned long long r;
    asm("mov.b64 %0, {%1, %2};" : "=l"(r) : "f"(x), "f"(y));
    return r;
}
__device__ __forceinline__ void unpack2(unsigned long long v, float& x, float& y) {
    asm("mov.b64 {%0, %1}, %2;" : "=f"(x), "=f"(y) : "l"(v));
}
__device__ __forceinline__ unsigned long long ffma2(unsigned long long a,
                                                    unsigned long long b,
                                                    unsigned long long c) {
    unsigned long long d;
    asm("fma.rn.f32x2 %0, %1, %2, %3;" : "=l"(d) : "l"(a), "l"(b), "l"(c));
    return d;
}

// ---------------------------------------------------------------------------
// Init: (a) index dtype detection — int64 buffer => first 64 values all in
// [0, 100000]; int32 read as int64 => (lo | hi<<32) out of range. (b) tril LUT.
// ---------------------------------------------------------------------------
__global__ void init_kernel(const long long* __restrict__ lsi) {
    if (threadIdx.x == 0) {
        int ok = 1;
        for (int i = 0; i < 64; i++) {
            long long v = lsi[i];
            if (v < 0 || v > 100000) { ok = 0; break; }
        }
        g_is64 = ok;
        int p = 0;
        for (int i = 1; i < NFEAT; i++)
            for (int j = 0; j < i; j++) {
                g_pi[p] = (unsigned char)i;
                g_pj[p] = (unsigned char)j;
                p++;
            }
    }
}

// ---------------------------------------------------------------------------
// Tiled SGEMM (R8-validated body):
//   C[m, n] = act( sum_k A[m*K+k] * W[n*K+k] + bias[n] ),  C stride = ldc.
// Register prefetch of tile t+1 during tile t compute; single smem buffer,
// two __syncthreads per tile. Acc packed 2-wide along M (FFMA2).
// ---------------------------------------------------------------------------
template<int BM, int BN, int BK, int TM, int TN, bool RELU>
__global__ void __launch_bounds__((BM / TM) * (BN / TN), 512 / ((BM / TM) * (BN / TN)))
sgemm_bias_act(const float* __restrict__ A, const float* __restrict__ W,
               const float* __restrict__ bias, float* __restrict__ C,
               int M, int N, int K, int ldc)
{
    constexpr int THREADS = (BM / TM) * (BN / TN);
    constexpr int LA = BM * BK / THREADS;    // per-thread A elements per tile
    constexpr int LW = BN * BK / THREADS;    // per-thread W elements per tile
    __shared__ float As[BK][BM + 4];
    __shared__ float Ws[BK][BN + 4];

    const int tid  = threadIdx.x;
    const int tx   = tid % (BN / TN);
    const int ty   = tid / (BN / TN);
    const int row0 = ty * TM;
    const int col0 = tx * TN;
    const int mBase = blockIdx.y * BM;
    const int nBase = blockIdx.x * BN;

    unsigned long long acc[TM / 2][TN];
    #pragma unroll
    for (int i = 0; i < TM / 2; i++)
        #pragma unroll
        for (int j = 0; j < TN; j++) acc[i][j] = 0ull;   // bits of (0.f,0.f)

    float pa[LA], pw[LW];

    // Prefetch tile 0 into registers
    {
        #pragma unroll
        for (int q = 0; q < LA; q++) {
            int e = tid + q * THREADS;
            int k = e % BK, m = e / BK;
            pa[q] = (k < K) ? A[(size_t)(mBase + m) * K + k] : 0.f;
        }
        #pragma unroll
        for (int q = 0; q < LW; q++) {
            int e = tid + q * THREADS;
            int k = e % BK, n = e / BK;
            int gn = nBase + n;
            pw[q] = (k < K && gn < N) ? W[(size_t)gn * K + k] : 0.f;
        }
    }

    const int nTiles = (K + BK - 1) / BK;
    for (int t = 0; t < nTiles; t++) {
        // Commit prefetched tile to smem
        #pragma unroll
        for (int q = 0; q < LA; q++) {
            int e = tid + q * THREADS;
            As[e % BK][e / BK] = pa[q];
        }
        #pragma unroll
        for (int q = 0; q < LW; q++) {
            int e = tid + q * THREADS;
            Ws[e % BK][e / BK] = pw[q];
        }
        __syncthreads();

        // Prefetch next tile while computing this one
        if (t + 1 < nTiles) {
            int k0 = (t + 1) * BK;
            #pragma unroll
            for (int q = 0; q < LA; q++) {
                int e = tid + q * THREADS;
                int k = e % BK, m = e / BK;
                int gk = k0 + k;
                pa[q] = (gk < K) ? A[(size_t)(mBase + m) * K + gk] : 0.f;
            }
            #pragma unroll
            for (int q = 0; q < LW; q++) {
                int e = tid + q * THREADS;
                int k = e % BK, n = e / BK;
                int gk = k0 + k, gn = nBase + n;
                pw[q] = (gk < K && gn < N) ? W[(size_t)gn * K + gk] : 0.f;
            }
        }

        #pragma unroll
        for (int kk = 0; kk < BK; kk++) {
            F4U a[TM / 4], w[TN / 4];
            #pragma unroll
            for (int q = 0; q < TM / 4; q++)
                a[q].f = *(const float4*)&As[kk][row0 + 4 * q];
            #pragma unroll
            for (int q = 0; q < TN / 4; q++)
                w[q].f = *(const float4*)&Ws[kk][col0 + 4 * q];

            unsigned long long au[TM / 2], bw[TN];
            #pragma unroll
            for (int q = 0; q < TM / 4; q++) {
                au[2 * q]     = a[q].u[0];     // pairs (m, m+1) straight from LDS.128
                au[2 * q + 1] = a[q].u[1];
            }
            #pragma unroll
            for (int q = 0; q < TN / 4; q++) {
                bw[4 * q + 0] = pack2(w[q].f.x, w[q].f.x);
                bw[4 * q + 1] = pack2(w[q].f.y, w[q].f.y);
                bw[4 * q + 2] = pack2(w[q].f.z, w[q].f.z);
                bw[4 * q + 3] = pack2(w[q].f.w, w[q].f.w);
            }
            #pragma unroll
            for (int mp = 0; mp < TM / 2; mp++)
                #pragma unroll
                for (int j = 0; j < TN; j++)
                    acc[mp][j] = ffma2(au[mp], bw[j], acc[mp][j]);
        }
        __syncthreads();
    }

    // Epilogue: bias + relu, scalar stores (ldc may be odd, e.g. 415)
    float bv[TN];
    #pragma unroll
    for (int j = 0; j < TN; j++) {
        int gn = nBase + col0 + j;
        bv[j] = (gn < N) ? bias[gn] : 0.f;
    }
    #pragma unroll
    for (int mp = 0; mp < TM / 2; mp++) {
        #pragma unroll
        for (int j = 0; j < TN; j++) {
            int gn = nBase + col0 + j;
            if (gn < N) {
                float c0, c1;
                unpack2(acc[mp][j], c0, c1);
                c0 += bv[j]; c1 += bv[j];
                if (RELU) { c0 = fmaxf(c0, 0.f); c1 = fmaxf(c1, 0.f); }
                size_t o = (size_t)(mBase + row0 + 2 * mp) * ldc + gn;
                C[o]       = c0;
                C[o + ldc] = c1;
            }
        }
    }
}

// ---------------------------------------------------------------------------
// FUSED gather + interaction. One block per batch row b.
// ---------------------------------------------------------------------------
__global__ void __launch_bounds__(384)
interact_kernel(const void* __restrict__ lsi_raw,
                const float* __restrict__ emb,
                float* __restrict__ R)
{
    __shared__ float T[NFEAT][68];
    __shared__ int   rowIdx[NTAB][LBAG];
    const int b = blockIdx.x;

    if (threadIdx.x < NTAB * LBAG) {
        const int t = threadIdx.x >> 2;
        const int l = threadIdx.x & 3;
        const long long ib = (long long)t * (BATCH * LBAG) + (long long)b * LBAG + l;
        long long r = (g_is64 != 0) ? ((const long long*)lsi_raw)[ib]
                                    : (long long)((const int*)lsi_raw)[ib];
        rowIdx[t][l] = (int)r;
    }
    for (int d = threadIdx.x; d < DDIM; d += 384)
        T[0][d] = R[(size_t)b * RCOLS + d];
    __syncthreads();

    for (int e = threadIdx.x; e < NTAB * (DDIM / 2); e += 384) {
        const int t  = e >> 5;
        const int d2 = e & 31;
        const float2* tab = (const float2*)(emb + (size_t)t * NROWS * DDIM) + d2;
        float sx = 0.f, sy = 0.f;
        #pragma unroll
        for (int l = 0; l < LBAG; l++) {
            float2 v = __ldg(tab + (size_t)rowIdx[t][l] * (DDIM / 2));
            sx += v.x; sy += v.y;
        }
        *(float2*)&T[1 + t][2 * d2] = make_float2(sx * 0.25f, sy * 0.25f);
    }
    __syncthreads();

    const int p = threadIdx.x;
    if (p < NPAIR) {
        const int i = __ldg(&g_pi[p]);
        const int j = __ldg(&g_pj[p]);
        const float4* ti = (const float4*)T[i];
        const float4* tj = (const float4*)T[j];
        float s = 0.f;
        #pragma unroll
        for (int k = 0; k < DDIM / 4; k++) {
            float4 a = ti[k], c = tj[k];
            s += a.x * c.x + a.y * c.y + a.z * c.z + a.w * c.w;
        }
        R[(size_t)b * RCOLS + DDIM + p] = s;
    }
}

// ---------------------------------------------------------------------------
// Final layer: z[b] = dot(t1[b, :256], w2) + b2. One warp per row.
// ---------------------------------------------------------------------------
__global__ void final_kernel(const float* __restrict__ t1,
                             const float* __restrict__ w2,
                             const float* __restrict__ b2,
                             float* __restrict__ out)
{
    const int warp = threadIdx.x >> 5;
    const int lane = threadIdx.x & 31;
    const int b = blockIdx.x * 8 + warp;

    const float4* x = (const float4*)(t1 + (size_t)b * 256);
    const float4* w = (const float4*)w2;
    float s = 0.f;
    #pragma unroll
    for (int k = lane; k < 64; k += 32) {
        float4 a = x[k], c = w[k];
        s += a.x * c.x + a.y * c.y + a.z * c.z + a.w * c.w;
    }
    #pragma unroll
    for (int off = 16; off; off >>= 1)
        s += __shfl_xor_sync(0xFFFFFFFFu, s, off);
    if (lane == 0) out[b] = s + b2[0];
}

// ---------------------------------------------------------------------------
// Launch
// ---------------------------------------------------------------------------
extern "C" void kernel_launch(void* const* d_in, const int* in_sizes, int n_in,
                              void* d_out, int out_size)
{
    const float* dense = (const float*)d_in[0];
    const void*  lsi   = d_in[2];                 // int64 or int32 (detected)
    const float* emb   = (const float*)d_in[3];
    const float* bw0 = (const float*)d_in[4];
    const float* bb0 = (const float*)d_in[5];
    const float* bw1 = (const float*)d_in[6];
    const float* bb1 = (const float*)d_in[7];
    const float* bw2 = (const float*)d_in[8];
    const float* bb2 = (const float*)d_in[9];
    const float* tw0 = (const float*)d_in[10];
    const float* tb0 = (const float*)d_in[11];
    const float* tw1 = (const float*)d_in[12];
    const float* tb1 = (const float*)d_in[13];
    const float* tw2 = (const float*)d_in[14];
    const float* tb2 = (const float*)d_in[15];

    float *h0, *h1, *R, *t0, *t1;
    cudaGetSymbolAddress((void**)&h0, g_h0);
    cudaGetSymbolAddress((void**)&h1, g_h1);
    cudaGetSymbolAddress((void**)&R,  g_R);
    cudaGetSymbolAddress((void**)&t0, g_t0);
    cudaGetSymbolAddress((void**)&t1, g_t1);

    init_kernel<<<1, 1>>>((const long long*)lsi);

    // Bottom MLP: 13 -> 512 -> 256 -> 64 (last layer writes R[:, 0:64])
    sgemm_bias_act<128, 64, 16, 8, 4, true><<<dim3(8, 64), 256>>>(
        dense, bw0, bb0, h0, BATCH, 512, 13, 512);
    sgemm_bias_act<128, 64, 32, 8, 4, true><<<dim3(4, 64), 256>>>(
        h0, bw1, bb1, h1, BATCH, 256, 512, 256);
    sgemm_bias_act<32, 64, 16, 4, 4, true><<<dim3(1, 256), 128>>>(
        h1, bw2, bb2, R, BATCH, 64, 256, RCOLS);

    // Fused gather + pairwise interaction -> R[:, 64:415]
    interact_kernel<<<BATCH, 384>>>(lsi, emb, R);

    // Top MLP: 415 -> 512 -> 256 -> 1
    sgemm_bias_act<128, 64, 32, 8, 4, true><<<dim3(8, 64), 256>>>(
        R, tw0, tb0, t0, BATCH, 512, RCOLS, 512);
    sgemm_bias_act<128, 64, 32, 8, 4, true><<<dim3(4, 64), 256>>>(
        t0, tw1, tb1, t1, BATCH, 256, 512, 256);
    final_kernel<<<BATCH / 8, 256>>>(t1, tw2, tb2, (float*)d_out);
}

// round 16
// speedup vs baseline: 1.5476x; 1.1862x over previous
#include <cuda_runtime.h>
#include <cuda_bf16.h>
#include <cstdint>

// ---------------------------------------------------------------------------
// DLRM forward. R15 (resubmitted; prior slot hit GPU acquisition timeout):
// bf16-split tensor-core GEMMs (mma.sync.m16n8k16) for bot2/bot3/top1/top2;
// D = Ahi*Whi + Ahi*Wlo + Alo*Whi (err ~2^-17).
// bot1 (K=13) stays on the validated fp32 FFMA2 path.
// Pipeline:
//   init: detect int64 vs int32 indices + build pair LUT (device side)
//   bot MLP: 13->512 (fp32) ->256 (mma) ->64 (mma, writes R[:,0:64])
//   interaction (FUSED gather+mean+351 pairwise dots) -> R[:,64:415]
//   top MLP: 415->512 (mma), 512->256 (mma), 256->1 (warp GEMV) -> d_out
// ---------------------------------------------------------------------------

#define BATCH 8192
#define NTAB  26
#define DDIM  64
#define LBAG  4
#define NROWS 100001
#define NFEAT 27
#define NPAIR 351
#define RCOLS 415

__device__ float g_h0[BATCH * 512];
__device__ float g_h1[BATCH * 256];
__device__ float g_R [(size_t)BATCH * RCOLS];
__device__ float g_t0[BATCH * 512];
__device__ float g_t1[BATCH * 256];
__device__ int   g_is64;
__device__ unsigned char g_pi[NPAIR];
__device__ unsigned char g_pj[NPAIR];

// ---------------------------------------------------------------------------
union F4U { float4 f; unsigned long long u[2]; };

__device__ __forceinline__ unsigned long long pack2(float x, float y) {
    unsigned long long r;
    asm("mov.b64 %0, {%1, %2};" : "=l"(r) : "f"(x), "f"(y));
    return r;
}
__device__ __forceinline__ void unpack2(unsigned long long v, float& x, float& y) {
    asm("mov.b64 {%0, %1}, %2;" : "=f"(x), "=f"(y) : "l"(v));
}
__device__ __forceinline__ unsigned long long ffma2(unsigned long long a,
                                                    unsigned long long b,
                                                    unsigned long long c) {
    unsigned long long d;
    asm("fma.rn.f32x2 %0, %1, %2, %3;" : "=l"(d) : "l"(a), "l"(b), "l"(c));
    return d;
}

// ---------------------------------------------------------------------------
__global__ void init_kernel(const long long* __restrict__ lsi) {
    if (threadIdx.x == 0) {
        int ok = 1;
        for (int i = 0; i < 64; i++) {
            long long v = lsi[i];
            if (v < 0 || v > 100000) { ok = 0; break; }
        }
        g_is64 = ok;
        int p = 0;
        for (int i = 1; i < NFEAT; i++)
            for (int j = 0; j < i; j++) {
                g_pi[p] = (unsigned char)i;
                g_pj[p] = (unsigned char)j;
                p++;
            }
    }
}

// ---------------------------------------------------------------------------
// bf16-split tensor-core GEMM: C[m,n] = act(sum_k A[m,k]*W[n,k] + bias[n]).
// CTA tile 64x64, 128 threads = 4 warps (2x2), warp tile 32x32.
// Smem: A/W tiles as bf16 hi+lo, [row][k] stride 40 (conflict-benign frags).
// mma.sync.aligned.m16n8k16.row.col.f32.bf16.bf16.f32, 3 combos per tile.
// ---------------------------------------------------------------------------
__device__ __forceinline__ void mma_bf16(float& c0, float& c1, float& c2, float& c3,
                                         unsigned a0, unsigned a1, unsigned a2, unsigned a3,
                                         unsigned b0, unsigned b1) {
    asm volatile(
        "mma.sync.aligned.m16n8k16.row.col.f32.bf16.bf16.f32 "
        "{%0,%1,%2,%3},{%4,%5,%6,%7},{%8,%9},{%0,%1,%2,%3};"
        : "+f"(c0), "+f"(c1), "+f"(c2), "+f"(c3)
        : "r"(a0), "r"(a1), "r"(a2), "r"(a3), "r"(b0), "r"(b1));
}

template<bool RELU>
__global__ void __launch_bounds__(128, 4)
mma_gemm(const float* __restrict__ A, const float* __restrict__ W,
         const float* __restrict__ bias, float* __restrict__ C,
         int M, int N, int K, int ldc)
{
    __shared__ __nv_bfloat16 Ah[64][40], Al[64][40], Wh[64][40], Wl[64][40];

    const int tid  = threadIdx.x;
    const int lane = tid & 31;
    const int warp = tid >> 5;
    const int g    = lane >> 2;        // group id (row within 8)
    const int tig  = lane & 3;         // thread in group
    const int wm   = (warp >> 1) * 32; // warp row offset in CTA tile
    const int wn   = (warp & 1) * 32;  // warp col offset
    const int mBase = blockIdx.y * 64;
    const int nBase = blockIdx.x * 64;

    float acc[2][4][4];
    #pragma unroll
    for (int i = 0; i < 2; i++)
        #pragma unroll
        for (int j = 0; j < 4; j++)
            #pragma unroll
            for (int r = 0; r < 4; r++) acc[i][j][r] = 0.f;

    for (int kt = 0; kt < K; kt += 32) {
        // Load + split-convert tiles into smem (bf16 hi + lo)
        #pragma unroll
        for (int q = 0; q < 16; q++) {
            int e = tid + q * 128;          // 0..2047 covers 64x32
            int m = e >> 5, k = e & 31;
            int gk = kt + k;
            float va = (gk < K) ? A[(size_t)(mBase + m) * K + gk] : 0.f;
            __nv_bfloat16 ha = __float2bfloat16(va);
            Ah[m][k] = ha;
            Al[m][k] = __float2bfloat16(va - __bfloat162float(ha));
            float vw = (gk < K) ? W[(size_t)(nBase + m) * K + gk] : 0.f;
            __nv_bfloat16 hw = __float2bfloat16(vw);
            Wh[m][k] = hw;
            Wl[m][k] = __float2bfloat16(vw - __bfloat162float(hw));
        }
        __syncthreads();

        #pragma unroll
        for (int ks = 0; ks < 32; ks += 16) {
            const int kc = ks + 2 * tig;
            // B fragments for 4 n-tiles (hi and lo)
            unsigned bh[4][2], bl[4][2];
            #pragma unroll
            for (int nj = 0; nj < 4; nj++) {
                int row = wn + nj * 8 + g;
                bh[nj][0] = *(const unsigned*)&Wh[row][kc];
                bh[nj][1] = *(const unsigned*)&Wh[row][kc + 8];
                bl[nj][0] = *(const unsigned*)&Wl[row][kc];
                bl[nj][1] = *(const unsigned*)&Wl[row][kc + 8];
            }
            #pragma unroll
            for (int mi = 0; mi < 2; mi++) {
                int ar = wm + mi * 16 + g;
                unsigned ah0 = *(const unsigned*)&Ah[ar][kc];
                unsigned ah1 = *(const unsigned*)&Ah[ar + 8][kc];
                unsigned ah2 = *(const unsigned*)&Ah[ar][kc + 8];
                unsigned ah3 = *(const unsigned*)&Ah[ar + 8][kc + 8];
                unsigned al0 = *(const unsigned*)&Al[ar][kc];
                unsigned al1 = *(const unsigned*)&Al[ar + 8][kc];
                unsigned al2 = *(const unsigned*)&Al[ar][kc + 8];
                unsigned al3 = *(const unsigned*)&Al[ar + 8][kc + 8];
                #pragma unroll
                for (int nj = 0; nj < 4; nj++) {
                    float* c = acc[mi][nj];
                    mma_bf16(c[0], c[1], c[2], c[3], ah0, ah1, ah2, ah3, bh[nj][0], bh[nj][1]);
                    mma_bf16(c[0], c[1], c[2], c[3], ah0, ah1, ah2, ah3, bl[nj][0], bl[nj][1]);
                    mma_bf16(c[0], c[1], c[2], c[3], al0, al1, al2, al3, bh[nj][0], bh[nj][1]);
                }
            }
        }
        __syncthreads();
    }

    // Epilogue: bias + optional relu. M, N are multiples of 64 -> no guards.
    #pragma unroll
    for (int mi = 0; mi < 2; mi++) {
        const int r0 = mBase + wm + mi * 16 + g;
        #pragma unroll
        for (int nj = 0; nj < 4; nj++) {
            const int cb = nBase + wn + nj * 8 + 2 * tig;
            const float b0 = bias[cb], b1 = bias[cb + 1];
            float v0 = acc[mi][nj][0] + b0;
            float v1 = acc[mi][nj][1] + b1;
            float v2 = acc[mi][nj][2] + b0;
            float v3 = acc[mi][nj][3] + b1;
            if (RELU) {
                v0 = fmaxf(v0, 0.f); v1 = fmaxf(v1, 0.f);
                v2 = fmaxf(v2, 0.f); v3 = fmaxf(v3, 0.f);
            }
            C[(size_t)r0 * ldc + cb]           = v0;
            C[(size_t)r0 * ldc + cb + 1]       = v1;
            C[(size_t)(r0 + 8) * ldc + cb]     = v2;
            C[(size_t)(r0 + 8) * ldc + cb + 1] = v3;
        }
    }
}

// ---------------------------------------------------------------------------
// fp32 FFMA2 SGEMM (R8-validated) — used only for bot1 (K=13).
// ---------------------------------------------------------------------------
template<int BM, int BN, int BK, int TM, int TN, bool RELU>
__global__ void __launch_bounds__((BM / TM) * (BN / TN), 512 / ((BM / TM) * (BN / TN)))
sgemm_bias_act(const float* __restrict__ A, const float* __restrict__ W,
               const float* __restrict__ bias, float* __restrict__ C,
               int M, int N, int K, int ldc)
{
    constexpr int THREADS = (BM / TM) * (BN / TN);
    constexpr int LA = BM * BK / THREADS;
    constexpr int LW = BN * BK / THREADS;
    __shared__ float As[BK][BM + 4];
    __shared__ float Ws[BK][BN + 4];

    const int tid  = threadIdx.x;
    const int tx   = tid % (BN / TN);
    const int ty   = tid / (BN / TN);
    const int row0 = ty * TM;
    const int col0 = tx * TN;
    const int mBase = blockIdx.y * BM;
    const int nBase = blockIdx.x * BN;

    unsigned long long acc[TM / 2][TN];
    #pragma unroll
    for (int i = 0; i < TM / 2; i++)
        #pragma unroll
        for (int j = 0; j < TN; j++) acc[i][j] = 0ull;

    float pa[LA], pw[LW];
    {
        #pragma unroll
        for (int q = 0; q < LA; q++) {
            int e = tid + q * THREADS;
            int k = e % BK, m = e / BK;
            pa[q] = (k < K) ? A[(size_t)(mBase + m) * K + k] : 0.f;
        }
        #pragma unroll
        for (int q = 0; q < LW; q++) {
            int e = tid + q * THREADS;
            int k = e % BK, n = e / BK;
            int gn = nBase + n;
            pw[q] = (k < K && gn < N) ? W[(size_t)gn * K + k] : 0.f;
        }
    }

    const int nTiles = (K + BK - 1) / BK;
    for (int t = 0; t < nTiles; t++) {
        #pragma unroll
        for (int q = 0; q < LA; q++) {
            int e = tid + q * THREADS;
            As[e % BK][e / BK] = pa[q];
        }
        #pragma unroll
        for (int q = 0; q < LW; q++) {
            int e = tid + q * THREADS;
            Ws[e % BK][e / BK] = pw[q];
        }
        __syncthreads();

        if (t + 1 < nTiles) {
            int k0 = (t + 1) * BK;
            #pragma unroll
            for (int q = 0; q < LA; q++) {
                int e = tid + q * THREADS;
                int k = e % BK, m = e / BK;
                int gk = k0 + k;
                pa[q] = (gk < K) ? A[(size_t)(mBase + m) * K + gk] : 0.f;
            }
            #pragma unroll
            for (int q = 0; q < LW; q++) {
                int e = tid + q * THREADS;
                int k = e % BK, n = e / BK;
                int gk = k0 + k, gn = nBase + n;
                pw[q] = (gk < K && gn < N) ? W[(size_t)gn * K + gk] : 0.f;
            }
        }

        #pragma unroll
        for (int kk = 0; kk < BK; kk++) {
            F4U a[TM / 4], w[TN / 4];
            #pragma unroll
            for (int q = 0; q < TM / 4; q++)
                a[q].f = *(const float4*)&As[kk][row0 + 4 * q];
            #pragma unroll
            for (int q = 0; q < TN / 4; q++)
                w[q].f = *(const float4*)&Ws[kk][col0 + 4 * q];

            unsigned long long au[TM / 2], bw[TN];
            #pragma unroll
            for (int q = 0; q < TM / 4; q++) {
                au[2 * q]     = a[q].u[0];
                au[2 * q + 1] = a[q].u[1];
            }
            #pragma unroll
            for (int q = 0; q < TN / 4; q++) {
                bw[4 * q + 0] = pack2(w[q].f.x, w[q].f.x);
                bw[4 * q + 1] = pack2(w[q].f.y, w[q].f.y);
                bw[4 * q + 2] = pack2(w[q].f.z, w[q].f.z);
                bw[4 * q + 3] = pack2(w[q].f.w, w[q].f.w);
            }
            #pragma unroll
            for (int mp = 0; mp < TM / 2; mp++)
                #pragma unroll
                for (int j = 0; j < TN; j++)
                    acc[mp][j] = ffma2(au[mp], bw[j], acc[mp][j]);
        }
        __syncthreads();
    }

    float bv[TN];
    #pragma unroll
    for (int j = 0; j < TN; j++) {
        int gn = nBase + col0 + j;
        bv[j] = (gn < N) ? bias[gn] : 0.f;
    }
    #pragma unroll
    for (int mp = 0; mp < TM / 2; mp++) {
        #pragma unroll
        for (int j = 0; j < TN; j++) {
            int gn = nBase + col0 + j;
            if (gn < N) {
                float c0, c1;
                unpack2(acc[mp][j], c0, c1);
                c0 += bv[j]; c1 += bv[j];
                if (RELU) { c0 = fmaxf(c0, 0.f); c1 = fmaxf(c1, 0.f); }
                size_t o = (size_t)(mBase + row0 + 2 * mp) * ldc + gn;
                C[o]       = c0;
                C[o + ldc] = c1;
            }
        }
    }
}

// ---------------------------------------------------------------------------
// FUSED gather + interaction. One block per batch row b.
// ---------------------------------------------------------------------------
__global__ void __launch_bounds__(384)
interact_kernel(const void* __restrict__ lsi_raw,
                const float* __restrict__ emb,
                float* __restrict__ R)
{
    __shared__ float T[NFEAT][68];
    __shared__ int   rowIdx[NTAB][LBAG];
    const int b = blockIdx.x;

    if (threadIdx.x < NTAB * LBAG) {
        const int t = threadIdx.x >> 2;
        const int l = threadIdx.x & 3;
        const long long ib = (long long)t * (BATCH * LBAG) + (long long)b * LBAG + l;
        long long r = (g_is64 != 0) ? ((const long long*)lsi_raw)[ib]
                                    : (long long)((const int*)lsi_raw)[ib];
        rowIdx[t][l] = (int)r;
    }
    for (int d = threadIdx.x; d < DDIM; d += 384)
        T[0][d] = R[(size_t)b * RCOLS + d];
    __syncthreads();

    for (int e = threadIdx.x; e < NTAB * (DDIM / 2); e += 384) {
        const int t  = e >> 5;
        const int d2 = e & 31;
        const float2* tab = (const float2*)(emb + (size_t)t * NROWS * DDIM) + d2;
        float sx = 0.f, sy = 0.f;
        #pragma unroll
        for (int l = 0; l < LBAG; l++) {
            float2 v = __ldg(tab + (size_t)rowIdx[t][l] * (DDIM / 2));
            sx += v.x; sy += v.y;
        }
        *(float2*)&T[1 + t][2 * d2] = make_float2(sx * 0.25f, sy * 0.25f);
    }
    __syncthreads();

    const int p = threadIdx.x;
    if (p < NPAIR) {
        const int i = __ldg(&g_pi[p]);
        const int j = __ldg(&g_pj[p]);
        const float4* ti = (const float4*)T[i];
        const float4* tj = (const float4*)T[j];
        float s = 0.f;
        #pragma unroll
        for (int k = 0; k < DDIM / 4; k++) {
            float4 a = ti[k], c = tj[k];
            s += a.x * c.x + a.y * c.y + a.z * c.z + a.w * c.w;
        }
        R[(size_t)b * RCOLS + DDIM + p] = s;
    }
}

// ---------------------------------------------------------------------------
// Final layer: z[b] = dot(t1[b, :256], w2) + b2. One warp per row.
// ---------------------------------------------------------------------------
__global__ void final_kernel(const float* __restrict__ t1,
                             const float* __restrict__ w2,
                             const float* __restrict__ b2,
                             float* __restrict__ out)
{
    const int warp = threadIdx.x >> 5;
    const int lane = threadIdx.x & 31;
    const int b = blockIdx.x * 8 + warp;

    const float4* x = (const float4*)(t1 + (size_t)b * 256);
    const float4* w = (const float4*)w2;
    float s = 0.f;
    #pragma unroll
    for (int k = lane; k < 64; k += 32) {
        float4 a = x[k], c = w[k];
        s += a.x * c.x + a.y * c.y + a.z * c.z + a.w * c.w;
    }
    #pragma unroll
    for (int off = 16; off; off >>= 1)
        s += __shfl_xor_sync(0xFFFFFFFFu, s, off);
    if (lane == 0) out[b] = s + b2[0];
}

// ---------------------------------------------------------------------------
// Launch
// ---------------------------------------------------------------------------
extern "C" void kernel_launch(void* const* d_in, const int* in_sizes, int n_in,
                              void* d_out, int out_size)
{
    const float* dense = (const float*)d_in[0];
    const void*  lsi   = d_in[2];
    const float* emb   = (const float*)d_in[3];
    const float* bw0 = (const float*)d_in[4];
    const float* bb0 = (const float*)d_in[5];
    const float* bw1 = (const float*)d_in[6];
    const float* bb1 = (const float*)d_in[7];
    const float* bw2 = (const float*)d_in[8];
    const float* bb2 = (const float*)d_in[9];
    const float* tw0 = (const float*)d_in[10];
    const float* tb0 = (const float*)d_in[11];
    const float* tw1 = (const float*)d_in[12];
    const float* tb1 = (const float*)d_in[13];
    const float* tw2 = (const float*)d_in[14];
    const float* tb2 = (const float*)d_in[15];

    float *h0, *h1, *R, *t0, *t1;
    cudaGetSymbolAddress((void**)&h0, g_h0);
    cudaGetSymbolAddress((void**)&h1, g_h1);
    cudaGetSymbolAddress((void**)&R,  g_R);
    cudaGetSymbolAddress((void**)&t0, g_t0);
    cudaGetSymbolAddress((void**)&t1, g_t1);

    init_kernel<<<1, 1>>>((const long long*)lsi);

    // Bottom MLP: 13 -> 512 (fp32) -> 256 (mma) -> 64 (mma, into R[:,0:64])
    sgemm_bias_act<128, 64, 16, 8, 4, true><<<dim3(8, 64), 256>>>(
        dense, bw0, bb0, h0, BATCH, 512, 13, 512);
    mma_gemm<true><<<dim3(4, 128), 128>>>(h0, bw1, bb1, h1, BATCH, 256, 512, 256);
    mma_gemm<true><<<dim3(1, 128), 128>>>(h1, bw2, bb2, R, BATCH, 64, 256, RCOLS);

    // Fused gather + pairwise interaction -> R[:, 64:415]
    interact_kernel<<<BATCH, 384>>>(lsi, emb, R);

    // Top MLP: 415 -> 512 (mma) -> 256 (mma) -> 1 (GEMV)
    mma_gemm<true><<<dim3(8, 128), 128>>>(R, tw0, tb0, t0, BATCH, 512, RCOLS, 512);
    mma_gemm<true><<<dim3(4, 128), 128>>>(t0, tw1, tb1, t1, BATCH, 256, 512, 256);
    final_kernel<<<BATCH / 8, 256>>>(t1, tw2, tb2, (float*)d_out);
}